// round 1
// baseline (speedup 1.0000x reference)
#include <cuda_runtime.h>
#include <cuda_bf16.h>
#include <math_constants.h>

// ---------------------------------------------------------------------------
// GAT_50861002719235: 3-layer GAT, N=50000, E=1.6M, H=4, D=32/32/47
// Strategy: CSR-by-dst gather (no atomics in hot loop), warp per (node, head).
// ---------------------------------------------------------------------------

#define NN 50000
#define EE 1600000
#define HH 4
#define FIN 100
#define HD 128          // H*D for layers 0/1
#define HC 188          // H*C for layer 2 (4*47)
#define CC 47
#define NEG_SLOPE 0.2f

// ---- scratch (device globals; no dynamic allocation allowed) ----
__device__ int   g_row_ptr[NN + 1];
__device__ int   g_cursor[NN];
__device__ int   g_col_src[EE];
__device__ float g_fs[NN * HC];   // per-layer transformed features (max cols 188)
__device__ float g_h [NN * HC];   // per-layer finalized output / next input
__device__ float g_el[NN * HH];
__device__ float g_er[NN * HH];

// ---------------------------------------------------------------------------
// CSR build
// ---------------------------------------------------------------------------
__global__ void zero_counts_k() {
    int i = blockIdx.x * blockDim.x + threadIdx.x;
    if (i < NN) g_cursor[i] = 0;
}

__global__ void count_k(const int* __restrict__ dst) {
    int e = blockIdx.x * blockDim.x + threadIdx.x;
    if (e < EE) atomicAdd(&g_cursor[dst[e]], 1);
}

// single-block exclusive scan of 50000 counts; writes row_ptr and resets
// cursor to the segment start offsets.
__global__ void scan_k() {
    __shared__ int sh[1024];
    const int chunk = (NN + 1023) / 1024;  // 49
    int t = threadIdx.x;
    int base = t * chunk;
    int local = 0;
    for (int i = 0; i < chunk; i++) {
        int idx = base + i;
        if (idx < NN) local += g_cursor[idx];
    }
    sh[t] = local;
    __syncthreads();
    // inclusive Hillis-Steele scan
    for (int o = 1; o < 1024; o <<= 1) {
        int v = (t >= o) ? sh[t - o] : 0;
        __syncthreads();
        sh[t] += v;
        __syncthreads();
    }
    int run = (t > 0) ? sh[t - 1] : 0;
    for (int i = 0; i < chunk; i++) {
        int idx = base + i;
        if (idx < NN) {
            int c = g_cursor[idx];
            g_row_ptr[idx] = run;
            g_cursor[idx]  = run;   // fill cursor starts here
            run += c;
        }
    }
    if (t == 1023) g_row_ptr[NN] = sh[1023];
}

__global__ void fill_k(const int* __restrict__ src, const int* __restrict__ dst) {
    int e = blockIdx.x * blockDim.x + threadIdx.x;
    if (e < EE) {
        int p = atomicAdd(&g_cursor[dst[e]], 1);
        g_col_src[p] = src[e];
    }
}

// ---------------------------------------------------------------------------
// GEMM: out[n, c] = sum_k A[n,k] * W[k,c].  32-row tile per block, one thread
// per output column. W stays in L1/L2 (64-96 KB), A tile staged in SMEM.
// ---------------------------------------------------------------------------
__global__ void gemm_k(const float* __restrict__ A, const float* __restrict__ W,
                       float* __restrict__ out, int K, int COLS) {
    __shared__ float sh[32 * 128];
    int n0 = blockIdx.x * 32;
    for (int idx = threadIdx.x; idx < 32 * K; idx += blockDim.x) {
        int r = idx / K, k = idx - r * K;
        int n = n0 + r;
        sh[r * K + k] = (n < NN) ? A[(long)n * K + k] : 0.f;
    }
    __syncthreads();
    int c = threadIdx.x;
    if (c >= COLS) return;
    float acc[32];
#pragma unroll
    for (int r = 0; r < 32; r++) acc[r] = 0.f;
    for (int k = 0; k < K; k++) {
        float w = W[(long)k * COLS + c];
#pragma unroll
        for (int r = 0; r < 32; r++) acc[r] += sh[r * K + k] * w;
    }
#pragma unroll
    for (int r = 0; r < 32; r++) {
        int n = n0 + r;
        if (n < NN) out[(long)n * COLS + c] = acc[r];
    }
}

// ---------------------------------------------------------------------------
// el/er: one warp per (n, h);  el[n,h] = sum_d fs[n,h,d]*al[h,d]
// ---------------------------------------------------------------------------
__global__ void elr_k(const float* __restrict__ fs, const float* __restrict__ al,
                      const float* __restrict__ ar, int Dh, int COLS) {
    int w = (blockIdx.x * blockDim.x + threadIdx.x) >> 5;
    int lane = threadIdx.x & 31;
    if (w >= NN * HH) return;
    int n = w / HH, h = w - n * HH;
    float sl = 0.f, sr = 0.f;
    for (int d = lane; d < Dh; d += 32) {
        float v = fs[(long)n * COLS + h * Dh + d];
        sl += v * al[h * Dh + d];
        sr += v * ar[h * Dh + d];
    }
#pragma unroll
    for (int o = 16; o; o >>= 1) {
        sl += __shfl_xor_sync(0xffffffffu, sl, o);
        sr += __shfl_xor_sync(0xffffffffu, sr, o);
    }
    if (lane == 0) {
        g_el[n * HH + h] = sl;
        g_er[n * HH + h] = sr;
    }
}

// ---------------------------------------------------------------------------
// Gather + edge softmax + aggregate + finalize.  One warp per (n, h).
// Pass 1: max over incident edges (e = lrelu(el[src]+er[n])).
// Pass 2: exp-sum + accumulate ex * fs[src, h, d], lanes own d (and d+32 for
//         Dh=47).  Normalize by sum, optional ReLU.
// ---------------------------------------------------------------------------
__global__ void gather_k(const float* __restrict__ fs, float* __restrict__ out,
                         int Dh, int COLS, int relu_flag) {
    int w = (blockIdx.x * blockDim.x + threadIdx.x) >> 5;
    int lane = threadIdx.x & 31;
    if (w >= NN * HH) return;
    int n = w / HH, h = w - n * HH;
    int beg = g_row_ptr[n], end = g_row_ptr[n + 1];
    float er_n = g_er[n * HH + h];

    // pass 1: max
    float m = -CUDART_INF_F;
    for (int i = beg + lane; i < end; i += 32) {
        int s = g_col_src[i];
        float e = g_el[s * HH + h] + er_n;
        e = (e >= 0.f) ? e : NEG_SLOPE * e;
        m = fmaxf(m, e);
    }
#pragma unroll
    for (int o = 16; o; o >>= 1) m = fmaxf(m, __shfl_xor_sync(0xffffffffu, m, o));

    // pass 2: exp-sum + weighted accumulate
    float ssum = 0.f, acc0 = 0.f, acc1 = 0.f;
    int d0 = lane, d1 = lane + 32;
    for (int i0 = beg; i0 < end; i0 += 32) {
        int i = i0 + lane;
        int s = 0;
        float ex = 0.f;
        if (i < end) {
            s = g_col_src[i];
            float e = g_el[s * HH + h] + er_n;
            e = (e >= 0.f) ? e : NEG_SLOPE * e;
            ex = __expf(e - m);
            ssum += ex;
        }
        int cnt = min(32, end - i0);
        for (int j = 0; j < cnt; j++) {
            int sj = __shfl_sync(0xffffffffu, s, j);
            float exj = __shfl_sync(0xffffffffu, ex, j);
            const float* row = fs + (long)sj * COLS + h * Dh;
            acc0 += exj * row[d0];
            if (d1 < Dh) acc1 += exj * row[d1];
        }
    }
#pragma unroll
    for (int o = 16; o; o >>= 1) ssum += __shfl_xor_sync(0xffffffffu, ssum, o);
    float inv = (ssum > 0.f) ? 1.f / ssum : 0.f;
    float o0 = acc0 * inv, o1 = acc1 * inv;
    if (relu_flag) { o0 = fmaxf(o0, 0.f); o1 = fmaxf(o1, 0.f); }
    out[(long)n * COLS + h * Dh + d0] = o0;
    if (d1 < Dh) out[(long)n * COLS + h * Dh + d1] = o1;
}

// ---------------------------------------------------------------------------
// Final: mean over heads + log_softmax over 47 classes. One warp per node.
// ---------------------------------------------------------------------------
__global__ void final_k(const float* __restrict__ hin, float* __restrict__ out) {
    int w = (blockIdx.x * blockDim.x + threadIdx.x) >> 5;
    int lane = threadIdx.x & 31;
    if (w >= NN) return;
    int n = w;
    float v0 = 0.f, v1 = 0.f;
    int c0 = lane, c1 = lane + 32;
    if (c0 < CC) {
#pragma unroll
        for (int h = 0; h < HH; h++) v0 += hin[(long)n * HC + h * CC + c0];
        v0 *= 0.25f;
    }
    if (c1 < CC) {
#pragma unroll
        for (int h = 0; h < HH; h++) v1 += hin[(long)n * HC + h * CC + c1];
        v1 *= 0.25f;
    }
    float a = (c0 < CC) ? v0 : -CUDART_INF_F;
    float b = (c1 < CC) ? v1 : -CUDART_INF_F;
    float m = fmaxf(a, b);
#pragma unroll
    for (int o = 16; o; o >>= 1) m = fmaxf(m, __shfl_xor_sync(0xffffffffu, m, o));
    float s = 0.f;
    if (c0 < CC) s += __expf(v0 - m);
    if (c1 < CC) s += __expf(v1 - m);
#pragma unroll
    for (int o = 16; o; o >>= 1) s += __shfl_xor_sync(0xffffffffu, s, o);
    float lse = m + logf(s);
    if (c0 < CC) out[(long)n * CC + c0] = v0 - lse;
    if (c1 < CC) out[(long)n * CC + c1] = v1 - lse;
}

// ---------------------------------------------------------------------------
extern "C" void kernel_launch(void* const* d_in, const int* in_sizes, int n_in,
                              void* d_out, int out_size) {
    const float* x   = (const float*)d_in[0];
    const float* W0  = (const float*)d_in[1];
    const float* al0 = (const float*)d_in[2];
    const float* ar0 = (const float*)d_in[3];
    const float* W1  = (const float*)d_in[4];
    const float* al1 = (const float*)d_in[5];
    const float* ar1 = (const float*)d_in[6];
    const float* W2  = (const float*)d_in[7];
    const float* al2 = (const float*)d_in[8];
    const float* ar2 = (const float*)d_in[9];
    const int*   src = (const int*)d_in[10];
    const int*   dst = (const int*)d_in[11];
    float* out = (float*)d_out;

    float* fs = nullptr; float* hbuf = nullptr;
    float* el = nullptr; float* er = nullptr;
    cudaGetSymbolAddress((void**)&fs,  g_fs);
    cudaGetSymbolAddress((void**)&hbuf, g_h);

    // ---- CSR build ----
    zero_counts_k<<<(NN + 255) / 256, 256>>>();
    count_k<<<(EE + 255) / 256, 256>>>(dst);
    scan_k<<<1, 1024>>>();
    fill_k<<<(EE + 255) / 256, 256>>>(src, dst);

    const int gemm_blocks = (NN + 31) / 32;       // 1563
    const int nh_warps_blocks = (NN * HH * 32 + 255) / 256;   // 25000
    const int n_warps_blocks  = (NN * 32 + 255) / 256;        // 6250

    // ---- layer 0: x[N,100] -> h[N,128] ----
    gemm_k<<<gemm_blocks, 128>>>(x, W0, fs, FIN, HD);
    elr_k<<<nh_warps_blocks, 256>>>(fs, al0, ar0, 32, HD);
    gather_k<<<nh_warps_blocks, 256>>>(fs, hbuf, 32, HD, 1);

    // ---- layer 1: h[N,128] -> h[N,128] ----
    gemm_k<<<gemm_blocks, 128>>>(hbuf, W1, fs, HD, HD);
    elr_k<<<nh_warps_blocks, 256>>>(fs, al1, ar1, 32, HD);
    gather_k<<<nh_warps_blocks, 256>>>(fs, hbuf, 32, HD, 1);

    // ---- layer 2: h[N,128] -> h[N,188] ----
    gemm_k<<<gemm_blocks, 192>>>(hbuf, W2, fs, HD, HC);
    elr_k<<<nh_warps_blocks, 256>>>(fs, al2, ar2, CC, HC);
    gather_k<<<nh_warps_blocks, 256>>>(fs, hbuf, CC, HC, 0);

    // ---- head mean + log_softmax ----
    final_k<<<n_warps_blocks, 256>>>(hbuf, out);
}

// round 2
// speedup vs baseline: 1.5015x; 1.5015x over previous
#include <cuda_runtime.h>
#include <cuda_bf16.h>
#include <math_constants.h>

// ---------------------------------------------------------------------------
// GAT_50861002719235: 3-layer GAT, N=50000, E=1.6M, H=4, D=32/32/47
// CSR-by-dst gather, single-pass edge softmax via global-max shift.
// ---------------------------------------------------------------------------

#define NN 50000
#define EE 1600000
#define HH 4
#define FIN 100
#define HD 128          // H*D for layers 0/1
#define HC 188          // H*C for layer 2 (4*47)
#define CC 47
#define NEG_SLOPE 0.2f

// ---- scratch (device globals) ----
__device__ int   g_row_ptr[NN + 1];
__device__ int   g_cursor[NN];
__device__ int   g_col_src[EE];
__device__ float g_fs[NN * HC];     // transformed features (max cols 188)
__device__ float g_h [NN * HC];     // finalized output / next input
__device__ float g_el[HH * NN];     // TRANSPOSED: [h][n]
__device__ float g_er[NN * HH];     // interleaved: [n][h]
__device__ float g_maxel[HH];       // per-head global max of el

__device__ __forceinline__ float lrelu(float x) {
    return (x >= 0.f) ? x : NEG_SLOPE * x;
}

// ---------------------------------------------------------------------------
// CSR build
// ---------------------------------------------------------------------------
__global__ void zero_counts_k() {
    int i = blockIdx.x * blockDim.x + threadIdx.x;
    if (i < NN) g_cursor[i] = 0;
}

__global__ void count_k(const int* __restrict__ dst) {
    int e = blockIdx.x * blockDim.x + threadIdx.x;
    if (e < EE) atomicAdd(&g_cursor[dst[e]], 1);
}

__global__ void scan_k() {
    __shared__ int sh[1024];
    const int chunk = (NN + 1023) / 1024;  // 49
    int t = threadIdx.x;
    int base = t * chunk;
    int local = 0;
    for (int i = 0; i < chunk; i++) {
        int idx = base + i;
        if (idx < NN) local += g_cursor[idx];
    }
    sh[t] = local;
    __syncthreads();
    for (int o = 1; o < 1024; o <<= 1) {
        int v = (t >= o) ? sh[t - o] : 0;
        __syncthreads();
        sh[t] += v;
        __syncthreads();
    }
    int run = (t > 0) ? sh[t - 1] : 0;
    for (int i = 0; i < chunk; i++) {
        int idx = base + i;
        if (idx < NN) {
            int c = g_cursor[idx];
            g_row_ptr[idx] = run;
            g_cursor[idx]  = run;
            run += c;
        }
    }
    if (t == 1023) g_row_ptr[NN] = sh[1023];
}

__global__ void fill_k(const int* __restrict__ src, const int* __restrict__ dst) {
    int e = blockIdx.x * blockDim.x + threadIdx.x;
    if (e < EE) {
        int p = atomicAdd(&g_cursor[dst[e]], 1);
        g_col_src[p] = src[e];
    }
}

// ---------------------------------------------------------------------------
// GEMM: out[n,c] = sum_k A[n,k]*W[k,c]. 32-row tile, LDS.128 feeds 4 FMAs.
// ---------------------------------------------------------------------------
template<int K, int COLS, int TPB>
__global__ void gemm_k(const float* __restrict__ A, const float* __restrict__ W,
                       float* __restrict__ out) {
    __shared__ float sh[32 * K];
    int n0 = blockIdx.x * 32;
    const int nv = 32 * K / 4;
    const float4* A4 = (const float4*)(A + (long)n0 * K);
    float4* sh4 = (float4*)sh;
    if (n0 + 32 <= NN) {
        for (int idx = threadIdx.x; idx < nv; idx += TPB) sh4[idx] = A4[idx];
    } else {
        for (int idx = threadIdx.x; idx < nv; idx += TPB) {
            int n = n0 + (idx * 4) / K;
            sh4[idx] = (n < NN) ? A4[idx] : make_float4(0.f, 0.f, 0.f, 0.f);
        }
    }
    __syncthreads();
    int c = threadIdx.x;
    if (c >= COLS) return;
    float acc[32];
#pragma unroll
    for (int r = 0; r < 32; r++) acc[r] = 0.f;
    for (int k0 = 0; k0 < K; k0 += 4) {
        float w0 = W[(k0 + 0) * COLS + c];
        float w1 = W[(k0 + 1) * COLS + c];
        float w2 = W[(k0 + 2) * COLS + c];
        float w3 = W[(k0 + 3) * COLS + c];
#pragma unroll
        for (int r = 0; r < 32; r++) {
            float4 a = *(const float4*)&sh[r * K + k0];
            acc[r] += a.x * w0 + a.y * w1 + a.z * w2 + a.w * w3;
        }
    }
    int nmax = min(32, NN - n0);
    for (int r = 0; r < nmax; r++)
        out[(long)(n0 + r) * COLS + c] = acc[r];
}

// ---------------------------------------------------------------------------
// el/er: one warp per (n, h). el stored transposed [h][n].
// ---------------------------------------------------------------------------
__global__ void elr_k(const float* __restrict__ fs, const float* __restrict__ al,
                      const float* __restrict__ ar, int Dh, int COLS) {
    int w = (blockIdx.x * blockDim.x + threadIdx.x) >> 5;
    int lane = threadIdx.x & 31;
    if (w >= NN * HH) return;
    int n = w >> 2, h = w & 3;
    float sl = 0.f, sr = 0.f;
    for (int d = lane; d < Dh; d += 32) {
        float v = fs[(long)n * COLS + h * Dh + d];
        sl += v * al[h * Dh + d];
        sr += v * ar[h * Dh + d];
    }
#pragma unroll
    for (int o = 16; o; o >>= 1) {
        sl += __shfl_xor_sync(0xffffffffu, sl, o);
        sr += __shfl_xor_sync(0xffffffffu, sr, o);
    }
    if (lane == 0) {
        g_el[h * NN + n] = sl;
        g_er[n * HH + h] = sr;
    }
}

// per-head global max of el. One block per head, no atomics, no init needed.
__global__ void maxel_k() {
    __shared__ float sm[1024];
    int h = blockIdx.x;
    const float* elh = g_el + h * NN;
    float m = -CUDART_INF_F;
    for (int n = threadIdx.x; n < NN; n += 1024) m = fmaxf(m, elh[n]);
    sm[threadIdx.x] = m;
    __syncthreads();
    for (int o = 512; o >= 1; o >>= 1) {
        if (threadIdx.x < o) sm[threadIdx.x] = fmaxf(sm[threadIdx.x], sm[threadIdx.x + o]);
        __syncthreads();
    }
    if (threadIdx.x == 0) g_maxel[h] = sm[0];
}

// ---------------------------------------------------------------------------
// Single-pass gather + softmax + aggregate. One warp per (n, h).
// Shift m = lrelu(gmax_el[h] + er[n]) >= true per-node max (lrelu monotone),
// so exp args are <= 0: stable, and softmax is shift-invariant.
// ---------------------------------------------------------------------------
template<int DH, int COLS, bool RELU>
__global__ void gather_k(const float* __restrict__ fs, float* __restrict__ out) {
    int w = (blockIdx.x * blockDim.x + threadIdx.x) >> 5;
    int lane = threadIdx.x & 31;
    if (w >= NN * HH) return;
    int n = w >> 2, h = w & 3;
    int beg = g_row_ptr[n], end = g_row_ptr[n + 1];
    float er_n = g_er[n * HH + h];
    float m = lrelu(g_maxel[h] + er_n);
    const float* __restrict__ elh = g_el + h * NN;

    float ssum = 0.f, acc0 = 0.f, acc1 = 0.f;
    for (int i0 = beg; i0 < end; i0 += 32) {
        int i = i0 + lane;
        int s = 0;
        float ex = 0.f;
        if (i < end) {
            s = g_col_src[i];
            float e = lrelu(elh[s] + er_n);
            ex = __expf(e - m);
            ssum += ex;
        }
        int cnt = min(32, end - i0);
        if (cnt == 32) {
#pragma unroll
            for (int j = 0; j < 32; j++) {
                int sj = __shfl_sync(0xffffffffu, s, j);
                float exj = __shfl_sync(0xffffffffu, ex, j);
                const float* row = fs + (long)sj * COLS + h * DH;
                acc0 += exj * row[lane];
                if (DH > 32) { if (lane + 32 < DH) acc1 += exj * row[lane + 32]; }
            }
        } else {
            for (int j = 0; j < cnt; j++) {
                int sj = __shfl_sync(0xffffffffu, s, j);
                float exj = __shfl_sync(0xffffffffu, ex, j);
                const float* row = fs + (long)sj * COLS + h * DH;
                acc0 += exj * row[lane];
                if (DH > 32) { if (lane + 32 < DH) acc1 += exj * row[lane + 32]; }
            }
        }
    }
#pragma unroll
    for (int o = 16; o; o >>= 1) ssum += __shfl_xor_sync(0xffffffffu, ssum, o);
    float inv = (ssum > 0.f) ? 1.f / ssum : 0.f;
    float o0 = acc0 * inv;
    if (RELU) o0 = fmaxf(o0, 0.f);
    out[(long)n * COLS + h * DH + lane] = o0;
    if (DH > 32) {
        if (lane + 32 < DH) {
            float o1 = acc1 * inv;
            if (RELU) o1 = fmaxf(o1, 0.f);
            out[(long)n * COLS + h * DH + lane + 32] = o1;
        }
    }
}

// ---------------------------------------------------------------------------
// Final: mean over heads + log_softmax over 47 classes. One warp per node.
// ---------------------------------------------------------------------------
__global__ void final_k(const float* __restrict__ hin, float* __restrict__ out) {
    int w = (blockIdx.x * blockDim.x + threadIdx.x) >> 5;
    int lane = threadIdx.x & 31;
    if (w >= NN) return;
    int n = w;
    float v0 = 0.f, v1 = 0.f;
    int c0 = lane, c1 = lane + 32;
    if (c0 < CC) {
#pragma unroll
        for (int h = 0; h < HH; h++) v0 += hin[(long)n * HC + h * CC + c0];
        v0 *= 0.25f;
    }
    if (c1 < CC) {
#pragma unroll
        for (int h = 0; h < HH; h++) v1 += hin[(long)n * HC + h * CC + c1];
        v1 *= 0.25f;
    }
    float a = (c0 < CC) ? v0 : -CUDART_INF_F;
    float b = (c1 < CC) ? v1 : -CUDART_INF_F;
    float m = fmaxf(a, b);
#pragma unroll
    for (int o = 16; o; o >>= 1) m = fmaxf(m, __shfl_xor_sync(0xffffffffu, m, o));
    float s = 0.f;
    if (c0 < CC) s += __expf(v0 - m);
    if (c1 < CC) s += __expf(v1 - m);
#pragma unroll
    for (int o = 16; o; o >>= 1) s += __shfl_xor_sync(0xffffffffu, s, o);
    float lse = m + logf(s);
    if (c0 < CC) out[(long)n * CC + c0] = v0 - lse;
    if (c1 < CC) out[(long)n * CC + c1] = v1 - lse;
}

// ---------------------------------------------------------------------------
extern "C" void kernel_launch(void* const* d_in, const int* in_sizes, int n_in,
                              void* d_out, int out_size) {
    const float* x   = (const float*)d_in[0];
    const float* W0  = (const float*)d_in[1];
    const float* al0 = (const float*)d_in[2];
    const float* ar0 = (const float*)d_in[3];
    const float* W1  = (const float*)d_in[4];
    const float* al1 = (const float*)d_in[5];
    const float* ar1 = (const float*)d_in[6];
    const float* W2  = (const float*)d_in[7];
    const float* al2 = (const float*)d_in[8];
    const float* ar2 = (const float*)d_in[9];
    const int*   src = (const int*)d_in[10];
    const int*   dst = (const int*)d_in[11];
    float* out = (float*)d_out;

    float* fs = nullptr; float* hbuf = nullptr;
    cudaGetSymbolAddress((void**)&fs,  g_fs);
    cudaGetSymbolAddress((void**)&hbuf, g_h);

    // ---- CSR build ----
    zero_counts_k<<<(NN + 255) / 256, 256>>>();
    count_k<<<(EE + 255) / 256, 256>>>(dst);
    scan_k<<<1, 1024>>>();
    fill_k<<<(EE + 255) / 256, 256>>>(src, dst);

    const int gemm_blocks = (NN + 31) / 32;                   // 1563
    const int nh_warps_blocks = (NN * HH * 32 + 255) / 256;   // 25000
    const int n_warps_blocks  = (NN * 32 + 255) / 256;        // 6250

    // ---- layer 0: x[N,100] -> h[N,128] ----
    gemm_k<FIN, HD, 128><<<gemm_blocks, 128>>>(x, W0, fs);
    elr_k<<<nh_warps_blocks, 256>>>(fs, al0, ar0, 32, HD);
    maxel_k<<<HH, 1024>>>();
    gather_k<32, HD, true><<<nh_warps_blocks, 256>>>(fs, hbuf);

    // ---- layer 1: h[N,128] -> h[N,128] ----
    gemm_k<HD, HD, 128><<<gemm_blocks, 128>>>(hbuf, W1, fs);
    elr_k<<<nh_warps_blocks, 256>>>(fs, al1, ar1, 32, HD);
    maxel_k<<<HH, 1024>>>();
    gather_k<32, HD, true><<<nh_warps_blocks, 256>>>(fs, hbuf);

    // ---- layer 2: h[N,128] -> h[N,188] ----
    gemm_k<HD, HC, 192><<<gemm_blocks, 192>>>(hbuf, W2, fs);
    elr_k<<<nh_warps_blocks, 256>>>(fs, al2, ar2, CC, HC);
    maxel_k<<<HH, 1024>>>();
    gather_k<CC, HC, false><<<nh_warps_blocks, 256>>>(fs, hbuf);

    // ---- head mean + log_softmax ----
    final_k<<<n_warps_blocks, 256>>>(hbuf, out);
}

// round 3
// speedup vs baseline: 1.8996x; 1.2651x over previous
#include <cuda_runtime.h>
#include <cuda_bf16.h>
#include <math_constants.h>

// ---------------------------------------------------------------------------
// GAT_50861002719235: 3-layer GAT, N=50000, E=1.6M, H=4, D=32/32/47
// CSR-by-dst gather; warp-per-node 4-head vectorized aggregation.
// ---------------------------------------------------------------------------

#define NN 50000
#define EE 1600000
#define HH 4
#define FIN 100
#define HD 128          // H*D layers 0/1
#define CC 47
#define DP 48           // padded D for layer 2
#define HCP 192         // padded H*D layer 2 (4*48)
#define NEG_SLOPE 0.2f

// ---- scratch ----
__device__ int   g_row_ptr[NN + 1];
__device__ int   g_cursor[NN];
__device__ int   g_col_src[EE];
__device__ float g_fs[NN * HCP];    // transformed features (padded for L2)
__device__ float g_h [NN * HCP];    // finalized output / next input
__device__ float g_el[NN * HH];     // [n][h] float4-aligned
__device__ float g_er[NN * HH];     // [n][h]
__device__ float g_maxel[HH];       // per-head global max of el

__device__ __forceinline__ float lrelu(float x) { return (x >= 0.f) ? x : NEG_SLOPE * x; }
__device__ __forceinline__ float4 lrelu4(float4 v) {
    return make_float4(lrelu(v.x), lrelu(v.y), lrelu(v.z), lrelu(v.w));
}

// ---------------------------------------------------------------------------
// CSR build
// ---------------------------------------------------------------------------
__global__ void zero_counts_k() {
    int i = blockIdx.x * blockDim.x + threadIdx.x;
    if (i < NN) g_cursor[i] = 0;
}
__global__ void count_k(const int* __restrict__ dst) {
    int e = blockIdx.x * blockDim.x + threadIdx.x;
    if (e < EE) atomicAdd(&g_cursor[dst[e]], 1);
}
__global__ void scan_k() {
    __shared__ int sh[1024];
    const int chunk = (NN + 1023) / 1024;
    int t = threadIdx.x;
    int base = t * chunk;
    int local = 0;
    for (int i = 0; i < chunk; i++) { int idx = base + i; if (idx < NN) local += g_cursor[idx]; }
    sh[t] = local;
    __syncthreads();
    for (int o = 1; o < 1024; o <<= 1) {
        int v = (t >= o) ? sh[t - o] : 0;
        __syncthreads(); sh[t] += v; __syncthreads();
    }
    int run = (t > 0) ? sh[t - 1] : 0;
    for (int i = 0; i < chunk; i++) {
        int idx = base + i;
        if (idx < NN) { int c = g_cursor[idx]; g_row_ptr[idx] = run; g_cursor[idx] = run; run += c; }
    }
    if (t == 1023) g_row_ptr[NN] = sh[1023];
}
__global__ void fill_k(const int* __restrict__ src, const int* __restrict__ dst) {
    int e = blockIdx.x * blockDim.x + threadIdx.x;
    if (e < EE) { int p = atomicAdd(&g_cursor[dst[e]], 1); g_col_src[p] = src[e]; }
}

// ---------------------------------------------------------------------------
// GEMM layers 0/1: out[n,c] = sum_k A[n,k]*W[k,c].  32-row tile.
// ---------------------------------------------------------------------------
template<int K, int COLS, int TPB>
__global__ void gemm_k(const float* __restrict__ A, const float* __restrict__ W,
                       float* __restrict__ out) {
    __shared__ float sh[32 * K];
    int n0 = blockIdx.x * 32;
    const int nv = 32 * K / 4;
    const float4* A4 = (const float4*)(A + (long)n0 * K);
    float4* sh4 = (float4*)sh;
    if (n0 + 32 <= NN) {
        for (int idx = threadIdx.x; idx < nv; idx += TPB) sh4[idx] = A4[idx];
    } else {
        for (int idx = threadIdx.x; idx < nv; idx += TPB) {
            int n = n0 + (idx * 4) / K;
            sh4[idx] = (n < NN) ? A4[idx] : make_float4(0.f, 0.f, 0.f, 0.f);
        }
    }
    __syncthreads();
    int c = threadIdx.x;
    if (c >= COLS) return;
    float acc[32];
#pragma unroll
    for (int r = 0; r < 32; r++) acc[r] = 0.f;
    for (int k0 = 0; k0 < K; k0 += 4) {
        float w0 = W[(k0 + 0) * COLS + c];
        float w1 = W[(k0 + 1) * COLS + c];
        float w2 = W[(k0 + 2) * COLS + c];
        float w3 = W[(k0 + 3) * COLS + c];
#pragma unroll
        for (int r = 0; r < 32; r++) {
            float4 a = *(const float4*)&sh[r * K + k0];
            acc[r] += a.x * w0 + a.y * w1 + a.z * w2 + a.w * w3;
        }
    }
    int nmax = min(32, NN - n0);
    for (int r = 0; r < nmax; r++)
        out[(long)(n0 + r) * COLS + c] = acc[r];
}

// GEMM layer 2 with padded output [n][4][48]; pad col (d=47) zeroed.
__global__ void gemm2_k(const float* __restrict__ A, const float* __restrict__ W,
                        float* __restrict__ out) {
    const int K = HD, COLS = HH * CC, TPB = 192;
    __shared__ float sh[32 * K];
    int n0 = blockIdx.x * 32;
    const int nv = 32 * K / 4;
    const float4* A4 = (const float4*)(A + (long)n0 * K);
    float4* sh4 = (float4*)sh;
    if (n0 + 32 <= NN) {
        for (int idx = threadIdx.x; idx < nv; idx += TPB) sh4[idx] = A4[idx];
    } else {
        for (int idx = threadIdx.x; idx < nv; idx += TPB) {
            int n = n0 + (idx * 4) / K;
            sh4[idx] = (n < NN) ? A4[idx] : make_float4(0.f, 0.f, 0.f, 0.f);
        }
    }
    __syncthreads();
    int c = threadIdx.x;
    int nmax = min(32, NN - n0);
    if (c >= COLS) {
        // zero the pad column d=47 of head (c-188)
        if (c < COLS + HH) {
            int h = c - COLS;
            for (int r = 0; r < nmax; r++)
                out[(long)(n0 + r) * HCP + h * DP + (DP - 1)] = 0.f;
        }
        return;
    }
    float acc[32];
#pragma unroll
    for (int r = 0; r < 32; r++) acc[r] = 0.f;
    for (int k0 = 0; k0 < K; k0 += 4) {
        float w0 = W[(k0 + 0) * COLS + c];
        float w1 = W[(k0 + 1) * COLS + c];
        float w2 = W[(k0 + 2) * COLS + c];
        float w3 = W[(k0 + 3) * COLS + c];
#pragma unroll
        for (int r = 0; r < 32; r++) {
            float4 a = *(const float4*)&sh[r * K + k0];
            acc[r] += a.x * w0 + a.y * w1 + a.z * w2 + a.w * w3;
        }
    }
    int cp = (c / CC) * DP + (c % CC);   // padded column
    for (int r = 0; r < nmax; r++)
        out[(long)(n0 + r) * HCP + cp] = acc[r];
}

// ---------------------------------------------------------------------------
// elr layers 0/1: one warp per node, all 4 heads. fs row = 32 float4.
// 8-lane segmented reduction per head.
// ---------------------------------------------------------------------------
__global__ void elr_node_k(const float* __restrict__ fs, const float* __restrict__ al,
                           const float* __restrict__ ar) {
    int w = (blockIdx.x * blockDim.x + threadIdx.x) >> 5;
    int lane = threadIdx.x & 31;
    if (w >= NN) return;
    int n = w;
    float4 v  = ((const float4*)fs)[(long)n * 32 + lane];
    float4 a  = ((const float4*)al)[lane];
    float4 b  = ((const float4*)ar)[lane];
    float sl = v.x * a.x + v.y * a.y + v.z * a.z + v.w * a.w;
    float sr = v.x * b.x + v.y * b.y + v.z * b.z + v.w * b.w;
#pragma unroll
    for (int o = 1; o < 8; o <<= 1) {
        sl += __shfl_xor_sync(0xffffffffu, sl, o);
        sr += __shfl_xor_sync(0xffffffffu, sr, o);
    }
    if ((lane & 7) == 0) {
        int h = lane >> 3;
        g_el[n * HH + h] = sl;
        g_er[n * HH + h] = sr;
    }
}

// elr layer 2: one warp per (n,h), padded fs stride.
__global__ void elr2_k(const float* __restrict__ fs, const float* __restrict__ al,
                       const float* __restrict__ ar) {
    int w = (blockIdx.x * blockDim.x + threadIdx.x) >> 5;
    int lane = threadIdx.x & 31;
    if (w >= NN * HH) return;
    int n = w >> 2, h = w & 3;
    float sl = 0.f, sr = 0.f;
    for (int d = lane; d < CC; d += 32) {
        float v = fs[(long)n * HCP + h * DP + d];
        sl += v * al[h * CC + d];
        sr += v * ar[h * CC + d];
    }
#pragma unroll
    for (int o = 16; o; o >>= 1) {
        sl += __shfl_xor_sync(0xffffffffu, sl, o);
        sr += __shfl_xor_sync(0xffffffffu, sr, o);
    }
    if (lane == 0) { g_el[n * HH + h] = sl; g_er[n * HH + h] = sr; }
}

// per-head global max of el ([n][4] layout), single block.
__global__ void maxel_k() {
    __shared__ float4 sm[1024];
    const float4* el4 = (const float4*)g_el;
    float4 m = make_float4(-CUDART_INF_F, -CUDART_INF_F, -CUDART_INF_F, -CUDART_INF_F);
    for (int n = threadIdx.x; n < NN; n += 1024) {
        float4 v = el4[n];
        m.x = fmaxf(m.x, v.x); m.y = fmaxf(m.y, v.y);
        m.z = fmaxf(m.z, v.z); m.w = fmaxf(m.w, v.w);
    }
    sm[threadIdx.x] = m;
    __syncthreads();
    for (int o = 512; o >= 1; o >>= 1) {
        if (threadIdx.x < o) {
            float4 a = sm[threadIdx.x], b = sm[threadIdx.x + o];
            sm[threadIdx.x] = make_float4(fmaxf(a.x, b.x), fmaxf(a.y, b.y),
                                          fmaxf(a.z, b.z), fmaxf(a.w, b.w));
        }
        __syncthreads();
    }
    if (threadIdx.x < 4) g_maxel[threadIdx.x] = ((const float*)&sm[0])[threadIdx.x];
}

// ---------------------------------------------------------------------------
// Gather layers 0/1: one warp per node, all 4 heads at once.
// Row = 128 floats = 32 lanes x float4 -> 1 LDG.128 per edge.
// Edge coefficients staged in smem (float4 per edge), broadcast LDS reads.
// ---------------------------------------------------------------------------
template<bool RELU>
__global__ void gather_node_k(const float* __restrict__ fs, float* __restrict__ out) {
    __shared__ float4 sm_ex[8][32];
    int wib = threadIdx.x >> 5;
    int w = blockIdx.x * 8 + wib;
    int lane = threadIdx.x & 31;
    if (w >= NN) return;
    int n = w;
    int myh = lane >> 3;
    int beg = g_row_ptr[n], end = g_row_ptr[n + 1];
    float4 er4 = ((const float4*)g_er)[n];
    float4 mx4 = *(const float4*)g_maxel;
    float4 m4 = lrelu4(make_float4(mx4.x + er4.x, mx4.y + er4.y, mx4.z + er4.z, mx4.w + er4.w));

    const float4* fs4 = (const float4*)fs;
    float4 acc = make_float4(0.f, 0.f, 0.f, 0.f);
    float4 ssum = make_float4(0.f, 0.f, 0.f, 0.f);

    for (int i0 = beg; i0 < end; i0 += 32) {
        int i = i0 + lane;
        int s = 0;
        float4 ex = make_float4(0.f, 0.f, 0.f, 0.f);
        if (i < end) {
            s = g_col_src[i];
            float4 el4 = ((const float4*)g_el)[s];
            float4 e4 = lrelu4(make_float4(el4.x + er4.x, el4.y + er4.y,
                                           el4.z + er4.z, el4.w + er4.w));
            ex = make_float4(__expf(e4.x - m4.x), __expf(e4.y - m4.y),
                             __expf(e4.z - m4.z), __expf(e4.w - m4.w));
            ssum.x += ex.x; ssum.y += ex.y; ssum.z += ex.z; ssum.w += ex.w;
        }
        sm_ex[wib][lane] = ex;
        __syncwarp();
        int cnt = min(32, end - i0);
        const float* exbase = (const float*)&sm_ex[wib][0] + myh;
        if (cnt == 32) {
#pragma unroll
            for (int j = 0; j < 32; j++) {
                int sj = __shfl_sync(0xffffffffu, s, j);
                float exj = exbase[j * 4];
                float4 r = fs4[(long)sj * 32 + lane];
                acc.x += exj * r.x; acc.y += exj * r.y;
                acc.z += exj * r.z; acc.w += exj * r.w;
            }
        } else {
            for (int j = 0; j < cnt; j++) {
                int sj = __shfl_sync(0xffffffffu, s, j);
                float exj = exbase[j * 4];
                float4 r = fs4[(long)sj * 32 + lane];
                acc.x += exj * r.x; acc.y += exj * r.y;
                acc.z += exj * r.z; acc.w += exj * r.w;
            }
        }
        __syncwarp();
    }
    // reduce per-head exp sums across warp
#pragma unroll
    for (int o = 16; o; o >>= 1) {
        ssum.x += __shfl_xor_sync(0xffffffffu, ssum.x, o);
        ssum.y += __shfl_xor_sync(0xffffffffu, ssum.y, o);
        ssum.z += __shfl_xor_sync(0xffffffffu, ssum.z, o);
        ssum.w += __shfl_xor_sync(0xffffffffu, ssum.w, o);
    }
    float s_my = (myh == 0) ? ssum.x : (myh == 1) ? ssum.y : (myh == 2) ? ssum.z : ssum.w;
    float inv = (s_my > 0.f) ? 1.f / s_my : 0.f;
    float4 o4 = make_float4(acc.x * inv, acc.y * inv, acc.z * inv, acc.w * inv);
    if (RELU) {
        o4.x = fmaxf(o4.x, 0.f); o4.y = fmaxf(o4.y, 0.f);
        o4.z = fmaxf(o4.z, 0.f); o4.w = fmaxf(o4.w, 0.f);
    }
    ((float4*)out)[(long)n * 32 + lane] = o4;
}

// ---------------------------------------------------------------------------
// Gather layer 2 (padded D=48): row = 192 floats = 48 float4.
// Lane covers float4 idx lane and lane+32 (lane<16).
// ---------------------------------------------------------------------------
__global__ void gather2_node_k(const float* __restrict__ fs, float* __restrict__ out) {
    __shared__ float4 sm_ex[8][32];
    int wib = threadIdx.x >> 5;
    int w = blockIdx.x * 8 + wib;
    int lane = threadIdx.x & 31;
    if (w >= NN) return;
    int n = w;
    int ha = lane / 12;               // head of float4 idx lane  (lane*4/48)
    int hb = (lane + 32) / 12;        // head of float4 idx lane+32
    bool hasb = (lane < 16);
    int beg = g_row_ptr[n], end = g_row_ptr[n + 1];
    float4 er4 = ((const float4*)g_er)[n];
    float4 mx4 = *(const float4*)g_maxel;
    float4 m4 = lrelu4(make_float4(mx4.x + er4.x, mx4.y + er4.y, mx4.z + er4.z, mx4.w + er4.w));

    const float4* fs4 = (const float4*)fs;
    float4 acca = make_float4(0.f, 0.f, 0.f, 0.f);
    float4 accb = make_float4(0.f, 0.f, 0.f, 0.f);
    float4 ssum = make_float4(0.f, 0.f, 0.f, 0.f);

    for (int i0 = beg; i0 < end; i0 += 32) {
        int i = i0 + lane;
        int s = 0;
        float4 ex = make_float4(0.f, 0.f, 0.f, 0.f);
        if (i < end) {
            s = g_col_src[i];
            float4 el4 = ((const float4*)g_el)[s];
            float4 e4 = lrelu4(make_float4(el4.x + er4.x, el4.y + er4.y,
                                           el4.z + er4.z, el4.w + er4.w));
            ex = make_float4(__expf(e4.x - m4.x), __expf(e4.y - m4.y),
                             __expf(e4.z - m4.z), __expf(e4.w - m4.w));
            ssum.x += ex.x; ssum.y += ex.y; ssum.z += ex.z; ssum.w += ex.w;
        }
        sm_ex[wib][lane] = ex;
        __syncwarp();
        int cnt = min(32, end - i0);
        const float* exb = (const float*)&sm_ex[wib][0];
        for (int j = 0; j < cnt; j++) {
            int sj = __shfl_sync(0xffffffffu, s, j);
            float exja = exb[j * 4 + ha];
            long rb = (long)sj * 48;
            float4 r = fs4[rb + lane];
            acca.x += exja * r.x; acca.y += exja * r.y;
            acca.z += exja * r.z; acca.w += exja * r.w;
            if (hasb) {
                float exjb = exb[j * 4 + hb];
                float4 r2 = fs4[rb + 32 + lane];
                accb.x += exjb * r2.x; accb.y += exjb * r2.y;
                accb.z += exjb * r2.z; accb.w += exjb * r2.w;
            }
        }
        __syncwarp();
    }
#pragma unroll
    for (int o = 16; o; o >>= 1) {
        ssum.x += __shfl_xor_sync(0xffffffffu, ssum.x, o);
        ssum.y += __shfl_xor_sync(0xffffffffu, ssum.y, o);
        ssum.z += __shfl_xor_sync(0xffffffffu, ssum.z, o);
        ssum.w += __shfl_xor_sync(0xffffffffu, ssum.w, o);
    }
    const float* sarr = (const float*)&ssum;
    float sa = (ha == 0) ? ssum.x : (ha == 1) ? ssum.y : (ha == 2) ? ssum.z : ssum.w;
    float inva = (sa > 0.f) ? 1.f / sa : 0.f;
    float4 oa = make_float4(acca.x * inva, acca.y * inva, acca.z * inva, acca.w * inva);
    ((float4*)out)[(long)n * 48 + lane] = oa;
    if (hasb) {
        float sb = (hb == 0) ? ssum.x : (hb == 1) ? ssum.y : (hb == 2) ? ssum.z : ssum.w;
        float invb = (sb > 0.f) ? 1.f / sb : 0.f;
        float4 ob = make_float4(accb.x * invb, accb.y * invb, accb.z * invb, accb.w * invb);
        ((float4*)out)[(long)n * 48 + 32 + lane] = ob;
    }
    (void)sarr;
}

// ---------------------------------------------------------------------------
// Final: mean over heads (padded stride 48) + log_softmax over 47.
// ---------------------------------------------------------------------------
__global__ void final_k(const float* __restrict__ hin, float* __restrict__ out) {
    int w = (blockIdx.x * blockDim.x + threadIdx.x) >> 5;
    int lane = threadIdx.x & 31;
    if (w >= NN) return;
    int n = w;
    float v0 = 0.f, v1 = 0.f;
    int c0 = lane, c1 = lane + 32;
    if (c0 < CC) {
#pragma unroll
        for (int h = 0; h < HH; h++) v0 += hin[(long)n * HCP + h * DP + c0];
        v0 *= 0.25f;
    }
    if (c1 < CC) {
#pragma unroll
        for (int h = 0; h < HH; h++) v1 += hin[(long)n * HCP + h * DP + c1];
        v1 *= 0.25f;
    }
    float a = (c0 < CC) ? v0 : -CUDART_INF_F;
    float b = (c1 < CC) ? v1 : -CUDART_INF_F;
    float m = fmaxf(a, b);
#pragma unroll
    for (int o = 16; o; o >>= 1) m = fmaxf(m, __shfl_xor_sync(0xffffffffu, m, o));
    float s = 0.f;
    if (c0 < CC) s += __expf(v0 - m);
    if (c1 < CC) s += __expf(v1 - m);
#pragma unroll
    for (int o = 16; o; o >>= 1) s += __shfl_xor_sync(0xffffffffu, s, o);
    float lse = m + logf(s);
    if (c0 < CC) out[(long)n * CC + c0] = v0 - lse;
    if (c1 < CC) out[(long)n * CC + c1] = v1 - lse;
}

// ---------------------------------------------------------------------------
extern "C" void kernel_launch(void* const* d_in, const int* in_sizes, int n_in,
                              void* d_out, int out_size) {
    const float* x   = (const float*)d_in[0];
    const float* W0  = (const float*)d_in[1];
    const float* al0 = (const float*)d_in[2];
    const float* ar0 = (const float*)d_in[3];
    const float* W1  = (const float*)d_in[4];
    const float* al1 = (const float*)d_in[5];
    const float* ar1 = (const float*)d_in[6];
    const float* W2  = (const float*)d_in[7];
    const float* al2 = (const float*)d_in[8];
    const float* ar2 = (const float*)d_in[9];
    const int*   src = (const int*)d_in[10];
    const int*   dst = (const int*)d_in[11];
    float* out = (float*)d_out;

    float* fs = nullptr; float* hbuf = nullptr;
    cudaGetSymbolAddress((void**)&fs,  g_fs);
    cudaGetSymbolAddress((void**)&hbuf, g_h);

    // ---- CSR build ----
    zero_counts_k<<<(NN + 255) / 256, 256>>>();
    count_k<<<(EE + 255) / 256, 256>>>(dst);
    scan_k<<<1, 1024>>>();
    fill_k<<<(EE + 255) / 256, 256>>>(src, dst);

    const int gemm_blocks = (NN + 31) / 32;          // 1563
    const int node_blocks = (NN + 7) / 8;            // 6250 (8 warps/block)
    const int nh_blocks   = (NN * HH * 32 + 255) / 256;

    // ---- layer 0: x[N,100] -> h[N,128] ----
    gemm_k<FIN, HD, 128><<<gemm_blocks, 128>>>(x, W0, fs);
    elr_node_k<<<node_blocks, 256>>>(fs, al0, ar0);
    maxel_k<<<1, 1024>>>();
    gather_node_k<true><<<node_blocks, 256>>>(fs, hbuf);

    // ---- layer 1 ----
    gemm_k<HD, HD, 128><<<gemm_blocks, 128>>>(hbuf, W1, fs);
    elr_node_k<<<node_blocks, 256>>>(fs, al1, ar1);
    maxel_k<<<1, 1024>>>();
    gather_node_k<true><<<node_blocks, 256>>>(fs, hbuf);

    // ---- layer 2 (padded 4x48) ----
    gemm2_k<<<gemm_blocks, 192>>>(hbuf, W2, fs);
    elr2_k<<<nh_blocks, 256>>>(fs, al2, ar2);
    maxel_k<<<1, 1024>>>();
    gather2_node_k<<<node_blocks, 256>>>(fs, hbuf);

    // ---- head mean + log_softmax ----
    final_k<<<node_blocks, 256>>>(hbuf, out);
}